// round 13
// baseline (speedup 1.0000x reference)
#include <cuda_runtime.h>
#include <cuda_bf16.h>
#include <cuda_fp16.h>
#include <cstdint>

#define NN 50000
#define EE 1600000
#define DD 128
#define LN_EPS 1e-5f
#define SCAN_B 49   // ceil(NN / 1024)

// ---------------- scratch (static device globals) ---------------------------
__device__ float g_dinv[NN];
__device__ int   g_cnt[NN];
__device__ int   g_rowptr[NN + 1];
__device__ int   g_cursor[NN];
__device__ unsigned long long g_sstate[SCAN_B];   // lookback state (flag<<32 | value)
__device__ int2  g_edge[EE];                      // (src, ew bits)
__device__ __half g_xwh[(size_t)NN * DD];         // fp16 GEMM output (gather source)
__device__ __half g_xh[(size_t)NN * DD];          // fp16 current h (GEMM input + residual)
__device__ __half g_Wh[3 * DD * DD];              // fp16 weights

__device__ __forceinline__ uint32_t smem_to_u32(const void* p) {
    uint32_t a;
    asm("{ .reg .u64 t; cvta.to.shared.u64 t, %1; cvt.u32.u64 %0, t; }" : "=r"(a) : "l"(p));
    return a;
}

// ---------------- fp16 conversion (stream 2, overlaps graph build) -----------
__global__ __launch_bounds__(256) void k_conv(const float* __restrict__ x,
                                              const float* __restrict__ Ws) {
    int b = blockIdx.x, t = threadIdx.x;
    if (b < 25000) {
        int i = b * 256 + t;
        g_xh[i] = __float2half_rn(x[i]);
    } else {
        int j = (b - 25000) * 256 + t;     // < 49152
        g_Wh[j] = __float2half_rn(Ws[j]);
    }
}

// ---------------- count-only histogram ---------------------------------------
__global__ void k_cnt(const int* __restrict__ ei) {
    int e = blockIdx.x * blockDim.x + threadIdx.x;
    if (e < EE) atomicAdd(&g_cnt[ei[EE + e]], 1);
}

// ---------------- single-pass scan with decoupled lookback -------------------
__global__ __launch_bounds__(1024) void k_scan() {
    __shared__ int s_w[32];
    __shared__ int s_exc;
    int b = blockIdx.x, t = threadIdx.x, lane = t & 31, wid = t >> 5;
    int i = b * 1024 + t;
    int v = (i < NN) ? g_cnt[i] : 0;
    int incl = v;
    #pragma unroll
    for (int off = 1; off < 32; off <<= 1) {
        int u = __shfl_up_sync(0xffffffffu, incl, off);
        if (lane >= off) incl += u;
    }
    if (lane == 31) s_w[wid] = incl;
    __syncthreads();
    if (wid == 0) {
        int w = s_w[lane];
        #pragma unroll
        for (int off = 1; off < 32; off <<= 1) {
            int u = __shfl_up_sync(0xffffffffu, w, off);
            if (lane >= off) w += u;
        }
        s_w[lane] = w;
    }
    __syncthreads();
    int base = (wid == 0) ? 0 : s_w[wid - 1];
    unsigned int A = (unsigned int)s_w[31];    // block aggregate

    if (t == 0) {
        if (b == 0) {
            atomicExch(&g_sstate[0], (2ULL << 32) | A);   // PREFIX
            s_exc = 0;
        } else {
            atomicExch(&g_sstate[b], (1ULL << 32) | A);   // AGG
            unsigned int exc = 0;
            int idx = b - 1;
            while (true) {
                unsigned long long s = *((volatile unsigned long long*)&g_sstate[idx]);
                unsigned int f = (unsigned int)(s >> 32);
                if (f == 2u) { exc += (unsigned int)s; break; }
                if (f == 1u) { exc += (unsigned int)s; idx--; }
            }
            atomicExch(&g_sstate[b], (2ULL << 32) | (exc + A));
            s_exc = (int)exc;
        }
    }
    __syncthreads();
    if (i < NN) {
        int rp = s_exc + base + incl - v;
        g_rowptr[i] = rp;
        g_cursor[i] = rp;
        if (i == 0) g_rowptr[NN] = EE;
    }
}

// ---------------- CSR fill (raw ew, no norm) ---------------------------------
__global__ void k_fill(const int* __restrict__ ei, const float* __restrict__ ew) {
    int e = blockIdx.x * blockDim.x + threadIdx.x;
    if (e < EE) {
        int r = ei[e];
        int c = ei[EE + e];
        int pos = atomicAdd(&g_cursor[c], 1);
        g_edge[pos] = make_int2(r, __float_as_int(ew[e]));
    }
}

// ---------------- per-node degree from CSR + dinv ----------------------------
__global__ __launch_bounds__(256) void k_deg() {
    int warp = threadIdx.x >> 5, lane = threadIdx.x & 31;
    int n = blockIdx.x * 8 + warp;
    int beg = __ldg(&g_rowptr[n]), end = __ldg(&g_rowptr[n + 1]);
    float sum = 0.0f;
    for (int j = beg + lane; j < end; j += 32)
        sum += __int_as_float(__ldg(&g_edge[j].y));
    #pragma unroll
    for (int off = 16; off >= 1; off >>= 1) sum += __shfl_xor_sync(0xffffffffu, sum, off);
    if (lane == 0) g_dinv[n] = rsqrtf(sum + 1.0f);   // + self loop
}

// ---------------- mma.sync fp16 GEMM (single pass): outh = fp16(A @ W^T) ----
#define PADB 136
#define TILE_B (128 * PADB * 2)
#define SMEM_MMA_TOTAL (2 * TILE_B)

__device__ __forceinline__ void ldsm_x4(uint32_t* r, uint32_t addr) {
    asm volatile("ldmatrix.sync.aligned.m8n8.x4.shared.b16 {%0,%1,%2,%3}, [%4];"
                 : "=r"(r[0]), "=r"(r[1]), "=r"(r[2]), "=r"(r[3]) : "r"(addr));
}
__device__ __forceinline__ void mma_f16(float* c, const uint32_t* a, const uint32_t* b) {
    asm volatile("mma.sync.aligned.m16n8k16.row.col.f32.f16.f16.f32 "
                 "{%0,%1,%2,%3}, {%4,%5,%6,%7}, {%8,%9}, {%0,%1,%2,%3};"
                 : "+f"(c[0]), "+f"(c[1]), "+f"(c[2]), "+f"(c[3])
                 : "r"(a[0]), "r"(a[1]), "r"(a[2]), "r"(a[3]), "r"(b[0]), "r"(b[1]));
}

__global__ __launch_bounds__(256) void k_mma(const __half* __restrict__ Ah,
                                             const __half* __restrict__ Wh,
                                             __half* __restrict__ outh) {
    extern __shared__ char smem[];
    uint32_t sbase = smem_to_u32(smem);
    int tid = threadIdx.x;
    int bm = blockIdx.x * 128;

    #pragma unroll
    for (int it = 0; it < 16; it++) {
        int idx = tid + it * 256;            // 0..4095
        int tile = idx >> 11;
        int g = idx & 2047;
        int r = g >> 4, c8 = g & 15;
        uint32_t dst = (uint32_t)tile * TILE_B + ((uint32_t)r * PADB + (uint32_t)c8 * 8) * 2;
        uint4 v = make_uint4(0, 0, 0, 0);
        if (tile == 0) {
            int gr = bm + r;
            if (gr < NN) v = *(const uint4*)(Ah + (size_t)gr * 128 + c8 * 8);
        } else {
            v = *(const uint4*)(Wh + r * 128 + c8 * 8);
        }
        *(uint4*)(smem + dst) = v;
    }
    __syncthreads();

    int lane = tid & 31, warp = tid >> 5;
    int wm = warp >> 1, wn = warp & 1;

    uint32_t aoff[2];
    #pragma unroll
    for (int mi = 0; mi < 2; mi++) {
        int row = wm * 32 + mi * 16 + (lane & 15);
        aoff[mi] = ((uint32_t)row * PADB + (uint32_t)(lane >> 4) * 8) * 2;
    }
    uint32_t boff[4];
    #pragma unroll
    for (int pi = 0; pi < 4; pi++) {
        int row = wn * 64 + pi * 16 + (lane & 7) + 8 * ((lane >> 4) & 1);
        boff[pi] = ((uint32_t)row * PADB + (uint32_t)((lane >> 3) & 1) * 8) * 2;
    }

    uint32_t sA = sbase, sW = sbase + TILE_B;

    float C[2][8][4];
    #pragma unroll
    for (int mi = 0; mi < 2; mi++)
        #pragma unroll
        for (int ni = 0; ni < 8; ni++)
            #pragma unroll
            for (int q = 0; q < 4; q++) C[mi][ni][q] = 0.0f;

    #pragma unroll
    for (int ks = 0; ks < 8; ks++) {
        uint32_t kadv = (uint32_t)ks * 32;
        uint32_t a[2][4], bw[4][4];
        #pragma unroll
        for (int mi = 0; mi < 2; mi++) ldsm_x4(a[mi], sA + aoff[mi] + kadv);
        #pragma unroll
        for (int pi = 0; pi < 4; pi++) ldsm_x4(bw[pi], sW + boff[pi] + kadv);
        #pragma unroll
        for (int mi = 0; mi < 2; mi++) {
            #pragma unroll
            for (int ni = 0; ni < 8; ni++) {
                mma_f16(C[mi][ni], a[mi], &bw[ni >> 1][(ni & 1) * 2]);
            }
        }
    }

    int g = lane >> 2, ctg = lane & 3;
    #pragma unroll
    for (int mi = 0; mi < 2; mi++) {
        int r0 = bm + wm * 32 + mi * 16 + g;
        #pragma unroll
        for (int ni = 0; ni < 8; ni++) {
            int col = wn * 64 + ni * 8 + ctg * 2;
            if (r0 < NN)
                *(__half2*)&outh[(size_t)r0 * 128 + col] =
                    __floats2half2_rn(C[mi][ni][0], C[mi][ni][1]);
            if (r0 + 8 < NN)
                *(__half2*)&outh[(size_t)(r0 + 8) * 128 + col] =
                    __floats2half2_rn(C[mi][ni][2], C[mi][ni][3]);
        }
    }
}

// ---------------- warp-per-node aggregate + LN + ReLU + residual ------------
// Inline norm: per edge w = ew * dinv[src]; dinv_c factored out of the sum.
// flags: bit0 relu, bit1 residual from fp32 hinf, bit2 write fp32 hout,
//        bit3 write fp16 xh (next-layer input)
__global__ __launch_bounds__(256) void k_agg(const __half* __restrict__ xwh,
                                             const float* __restrict__ hinf,
                                             __half* __restrict__ xh_io,
                                             const float* __restrict__ bias,
                                             const float* __restrict__ gamma,
                                             const float* __restrict__ beta,
                                             float* __restrict__ hout,
                                             int flags) {
    int warp = threadIdx.x >> 5, lane = threadIdx.x & 31;
    int n = blockIdx.x * 8 + warp;     // grid 6250 * 8 = 50000 exact
    int d0 = lane * 4;

    float a0 = 0.0f, a1 = 0.0f, a2 = 0.0f, a3 = 0.0f;

    int beg = __ldg(&g_rowptr[n]), end = __ldg(&g_rowptr[n + 1]);
    int j = beg;
    for (; j + 7 < end; j += 8) {
        int2 e0 = __ldg(&g_edge[j]);
        int2 e1 = __ldg(&g_edge[j + 1]);
        int2 e2 = __ldg(&g_edge[j + 2]);
        int2 e3 = __ldg(&g_edge[j + 3]);
        int2 e4 = __ldg(&g_edge[j + 4]);
        int2 e5 = __ldg(&g_edge[j + 5]);
        int2 e6 = __ldg(&g_edge[j + 6]);
        int2 e7 = __ldg(&g_edge[j + 7]);
        uint2 v0 = __ldg((const uint2*)(xwh + (size_t)e0.x * DD + d0));
        uint2 v1 = __ldg((const uint2*)(xwh + (size_t)e1.x * DD + d0));
        uint2 v2 = __ldg((const uint2*)(xwh + (size_t)e2.x * DD + d0));
        uint2 v3 = __ldg((const uint2*)(xwh + (size_t)e3.x * DD + d0));
        uint2 v4 = __ldg((const uint2*)(xwh + (size_t)e4.x * DD + d0));
        uint2 v5 = __ldg((const uint2*)(xwh + (size_t)e5.x * DD + d0));
        uint2 v6 = __ldg((const uint2*)(xwh + (size_t)e6.x * DD + d0));
        uint2 v7 = __ldg((const uint2*)(xwh + (size_t)e7.x * DD + d0));
        float w0 = __int_as_float(e0.y) * __ldg(&g_dinv[e0.x]);
        float w1 = __int_as_float(e1.y) * __ldg(&g_dinv[e1.x]);
        float w2 = __int_as_float(e2.y) * __ldg(&g_dinv[e2.x]);
        float w3 = __int_as_float(e3.y) * __ldg(&g_dinv[e3.x]);
        float w4 = __int_as_float(e4.y) * __ldg(&g_dinv[e4.x]);
        float w5 = __int_as_float(e5.y) * __ldg(&g_dinv[e5.x]);
        float w6 = __int_as_float(e6.y) * __ldg(&g_dinv[e6.x]);
        float w7 = __int_as_float(e7.y) * __ldg(&g_dinv[e7.x]);
        float2 p, q;
        p = __half22float2(*(const __half2*)&v0.x); q = __half22float2(*(const __half2*)&v0.y);
        a0 += w0 * p.x; a1 += w0 * p.y; a2 += w0 * q.x; a3 += w0 * q.y;
        p = __half22float2(*(const __half2*)&v1.x); q = __half22float2(*(const __half2*)&v1.y);
        a0 += w1 * p.x; a1 += w1 * p.y; a2 += w1 * q.x; a3 += w1 * q.y;
        p = __half22float2(*(const __half2*)&v2.x); q = __half22float2(*(const __half2*)&v2.y);
        a0 += w2 * p.x; a1 += w2 * p.y; a2 += w2 * q.x; a3 += w2 * q.y;
        p = __half22float2(*(const __half2*)&v3.x); q = __half22float2(*(const __half2*)&v3.y);
        a0 += w3 * p.x; a1 += w3 * p.y; a2 += w3 * q.x; a3 += w3 * q.y;
        p = __half22float2(*(const __half2*)&v4.x); q = __half22float2(*(const __half2*)&v4.y);
        a0 += w4 * p.x; a1 += w4 * p.y; a2 += w4 * q.x; a3 += w4 * q.y;
        p = __half22float2(*(const __half2*)&v5.x); q = __half22float2(*(const __half2*)&v5.y);
        a0 += w5 * p.x; a1 += w5 * p.y; a2 += w5 * q.x; a3 += w5 * q.y;
        p = __half22float2(*(const __half2*)&v6.x); q = __half22float2(*(const __half2*)&v6.y);
        a0 += w6 * p.x; a1 += w6 * p.y; a2 += w6 * q.x; a3 += w6 * q.y;
        p = __half22float2(*(const __half2*)&v7.x); q = __half22float2(*(const __half2*)&v7.y);
        a0 += w7 * p.x; a1 += w7 * p.y; a2 += w7 * q.x; a3 += w7 * q.y;
    }
    for (; j < end; j++) {
        int2 e = __ldg(&g_edge[j]);
        float w = __int_as_float(e.y) * __ldg(&g_dinv[e.x]);
        uint2 v = __ldg((const uint2*)(xwh + (size_t)e.x * DD + d0));
        float2 p = __half22float2(*(const __half2*)&v.x);
        float2 q = __half22float2(*(const __half2*)&v.y);
        a0 += w * p.x; a1 += w * p.y; a2 += w * q.x; a3 += w * q.y;
    }

    // apply dest factor + self term + bias
    float dinv_c = __ldg(&g_dinv[n]);
    uint2 sv = __ldg((const uint2*)(xwh + (size_t)n * DD + d0));
    float2 s01 = __half22float2(*(const __half2*)&sv.x);
    float2 s23 = __half22float2(*(const __half2*)&sv.y);
    float4 bv = __ldg((const float4*)&bias[d0]);
    a0 = dinv_c * (a0 + dinv_c * s01.x) + bv.x;
    a1 = dinv_c * (a1 + dinv_c * s01.y) + bv.y;
    a2 = dinv_c * (a2 + dinv_c * s23.x) + bv.z;
    a3 = dinv_c * (a3 + dinv_c * s23.y) + bv.w;

    // warp-level LayerNorm over 128 features (4 per lane)
    float s = a0 + a1 + a2 + a3;
    #pragma unroll
    for (int off = 16; off >= 1; off >>= 1) s += __shfl_xor_sync(0xffffffffu, s, off);
    float mu = s * (1.0f / 128.0f);

    float d0f = a0 - mu, d1f = a1 - mu, d2f = a2 - mu, d3f = a3 - mu;
    float q = d0f * d0f + d1f * d1f + d2f * d2f + d3f * d3f;
    #pragma unroll
    for (int off = 16; off >= 1; off >>= 1) q += __shfl_xor_sync(0xffffffffu, q, off);
    float rstd = rsqrtf(q * (1.0f / 128.0f) + LN_EPS);

    float4 gv = __ldg((const float4*)&gamma[d0]);
    float4 bt = __ldg((const float4*)&beta[d0]);
    float y0 = d0f * rstd * gv.x + bt.x;
    float y1 = d1f * rstd * gv.y + bt.y;
    float y2 = d2f * rstd * gv.z + bt.z;
    float y3 = d3f * rstd * gv.w + bt.w;
    if (flags & 1) {
        y0 = fmaxf(y0, 0.0f); y1 = fmaxf(y1, 0.0f);
        y2 = fmaxf(y2, 0.0f); y3 = fmaxf(y3, 0.0f);
    }

    if (flags & 2) {
        float4 hv = __ldg((const float4*)&hinf[(size_t)n * DD + d0]);
        y0 += hv.x; y1 += hv.y; y2 += hv.z; y3 += hv.w;
    } else {
        uint2 hv = __ldg((const uint2*)(xh_io + (size_t)n * DD + d0));
        float2 h01 = __half22float2(*(const __half2*)&hv.x);
        float2 h23 = __half22float2(*(const __half2*)&hv.y);
        y0 += h01.x; y1 += h01.y; y2 += h23.x; y3 += h23.y;
    }

    if (flags & 4)
        *(float4*)&hout[(size_t)n * DD + d0] = make_float4(y0, y1, y2, y3);
    if (flags & 8) {
        size_t i = (size_t)n * DD + d0;
        __half2 h01 = __floats2half2_rn(y0, y1);
        __half2 h23 = __floats2half2_rn(y2, y3);
        *(uint2*)&xh_io[i] = make_uint2(*(uint32_t*)&h01, *(uint32_t*)&h23);
    }
}

// ---------------- launch ----------------------------------------------------
extern "C" void kernel_launch(void* const* d_in, const int* in_sizes, int n_in,
                              void* d_out, int out_size) {
    const float* x      = (const float*)d_in[0];
    const int*   ei     = (const int*)  d_in[1];
    const float* ew     = (const float*)d_in[2];
    const float* Ws     = (const float*)d_in[3];
    const float* bs     = (const float*)d_in[4];
    const float* gammas = (const float*)d_in[5];
    const float* betas  = (const float*)d_in[6];
    float* out = (float*)d_out;

    __half* xwh = nullptr; cudaGetSymbolAddress((void**)&xwh, g_xwh);
    __half* xh  = nullptr; cudaGetSymbolAddress((void**)&xh, g_xh);
    __half* Wh  = nullptr; cudaGetSymbolAddress((void**)&Wh, g_Wh);
    int*   cntp = nullptr; cudaGetSymbolAddress((void**)&cntp, g_cnt);
    void*  sstp = nullptr; cudaGetSymbolAddress(&sstp, g_sstate);

    cudaFuncSetAttribute(k_mma, cudaFuncAttributeMaxDynamicSharedMemorySize, SMEM_MMA_TOTAL);

    static cudaStream_t s2 = nullptr;
    static cudaEvent_t evFork = nullptr, evJoin = nullptr;
    if (!s2) {
        cudaStreamCreateWithFlags(&s2, cudaStreamNonBlocking);
        cudaEventCreateWithFlags(&evFork, cudaEventDisableTiming);
        cudaEventCreateWithFlags(&evJoin, cudaEventDisableTiming);
    }

    int gE = (EE + 255) / 256;                 // 6250
    int gConv = 25192;
    int gMma = (NN + 127) / 128;
    int gAgg = NN / 8;

    // fork at the very start: conversion + layer-0 GEMM on stream 2
    cudaEventRecord(evFork, 0);
    cudaStreamWaitEvent(s2, evFork, 0);
    k_conv<<<gConv, 256, 0, s2>>>(x, Ws);
    k_mma<<<gMma, 256, SMEM_MMA_TOTAL, s2>>>(xh, Wh + 0 * DD * DD, xwh);
    cudaEventRecord(evJoin, s2);

    // graph build on the main stream
    cudaMemsetAsync(cntp, 0, NN * sizeof(int));
    cudaMemsetAsync(sstp, 0, SCAN_B * sizeof(unsigned long long));
    k_cnt<<<gE, 256>>>(ei);
    k_scan<<<SCAN_B, 1024>>>();
    k_fill<<<gE, 256>>>(ei, ew);
    k_deg<<<gAgg, 256>>>();
    cudaStreamWaitEvent(0, evJoin, 0);

    // layer 0: residual from fp32 x; write fp16 xh only
    k_agg<<<gAgg, 256>>>(xwh, x, xh, bs + 0 * DD, gammas + 0 * DD, betas + 0 * DD, out, 1 | 2 | 8);
    // layer 1: residual fp16 xh; write fp16 xh
    k_mma<<<gMma, 256, SMEM_MMA_TOTAL>>>(xh, Wh + 1 * DD * DD, xwh);
    k_agg<<<gAgg, 256>>>(xwh, x, xh, bs + 1 * DD, gammas + 1 * DD, betas + 1 * DD, out, 1 | 8);
    // layer 2: residual fp16 xh; write fp32 out
    k_mma<<<gMma, 256, SMEM_MMA_TOTAL>>>(xh, Wh + 2 * DD * DD, xwh);
    k_agg<<<gAgg, 256>>>(xwh, x, xh, bs + 2 * DD, gammas + 2 * DD, betas + 2 * DD, out, 4);
}

// round 15
// speedup vs baseline: 1.2508x; 1.2508x over previous
#include <cuda_runtime.h>
#include <cuda_bf16.h>
#include <cuda_fp16.h>
#include <cstdint>

#define NN 50000
#define EE 1600000
#define DD 128
#define LN_EPS 1e-5f
#define SCAN_B 49   // ceil(NN / 1024)

// ---------------- scratch (static device globals) ---------------------------
__device__ float g_deg[NN];
__device__ float g_dinv[NN];
__device__ int   g_cnt[NN];
__device__ int   g_rowptr[NN + 1];
__device__ int   g_cursor[NN];
__device__ unsigned long long g_sstate[SCAN_B];   // lookback state (flag<<32 | value)
__device__ int2  g_edge[EE];                      // (src, norm bits)
__device__ __half g_xwh[(size_t)NN * DD];         // fp16 GEMM output (gather source)
__device__ __half g_xh[(size_t)NN * DD];          // fp16 current h (GEMM input + residual)
__device__ __half g_Wh[3 * DD * DD];              // fp16 weights

__device__ __forceinline__ uint32_t smem_to_u32(const void* p) {
    uint32_t a;
    asm("{ .reg .u64 t; cvta.to.shared.u64 t, %1; cvt.u32.u64 %0, t; }" : "=r"(a) : "l"(p));
    return a;
}

// ---------------- fp16 conversion (stream 2, overlaps graph build) -----------
__global__ __launch_bounds__(256) void k_conv(const float* __restrict__ x,
                                              const float* __restrict__ Ws) {
    int b = blockIdx.x, t = threadIdx.x;
    if (b < 25000) {
        int i = b * 256 + t;
        g_xh[i] = __float2half_rn(x[i]);
    } else {
        int j = (b - 25000) * 256 + t;     // < 49152
        g_Wh[j] = __float2half_rn(Ws[j]);
    }
}

// ---------------- degree + count histogram (main stream) ---------------------
__global__ void k_degcnt(const int* __restrict__ ei, const float* __restrict__ ew) {
    int e = blockIdx.x * blockDim.x + threadIdx.x;
    if (e < EE) {
        int c = ei[EE + e];
        atomicAdd(&g_deg[c], ew[e]);
        atomicAdd(&g_cnt[c], 1);
    }
}

// ---------------- single-pass lookback scan + cursor + dinv ------------------
__global__ __launch_bounds__(1024) void k_scan() {
    __shared__ int s_w[32];
    __shared__ int s_exc;
    int b = blockIdx.x, t = threadIdx.x, lane = t & 31, wid = t >> 5;
    int i = b * 1024 + t;
    int v = (i < NN) ? g_cnt[i] : 0;
    int incl = v;
    #pragma unroll
    for (int off = 1; off < 32; off <<= 1) {
        int u = __shfl_up_sync(0xffffffffu, incl, off);
        if (lane >= off) incl += u;
    }
    if (lane == 31) s_w[wid] = incl;
    __syncthreads();
    if (wid == 0) {
        int w = s_w[lane];
        #pragma unroll
        for (int off = 1; off < 32; off <<= 1) {
            int u = __shfl_up_sync(0xffffffffu, w, off);
            if (lane >= off) w += u;
        }
        s_w[lane] = w;
    }
    __syncthreads();
    int base = (wid == 0) ? 0 : s_w[wid - 1];
    unsigned int A = (unsigned int)s_w[31];

    if (t == 0) {
        if (b == 0) {
            atomicExch(&g_sstate[0], (2ULL << 32) | A);
            s_exc = 0;
        } else {
            atomicExch(&g_sstate[b], (1ULL << 32) | A);
            unsigned int exc = 0;
            int idx = b - 1;
            while (true) {
                unsigned long long s = *((volatile unsigned long long*)&g_sstate[idx]);
                unsigned int f = (unsigned int)(s >> 32);
                if (f == 2u) { exc += (unsigned int)s; break; }
                if (f == 1u) { exc += (unsigned int)s; idx--; }
            }
            atomicExch(&g_sstate[b], (2ULL << 32) | (exc + A));
            s_exc = (int)exc;
        }
    }
    __syncthreads();
    if (i < NN) {
        int rp = s_exc + base + incl - v;
        g_rowptr[i] = rp;
        g_cursor[i] = rp;
        float dg = g_deg[i] + 1.0f;     // + self-loop (deg memset to 0)
        g_dinv[i] = rsqrtf(dg);
        if (i == 0) g_rowptr[NN] = EE;
    }
}

// ---------------- CSR fill with precomputed norm -----------------------------
__global__ void k_fill(const int* __restrict__ ei, const float* __restrict__ ew) {
    int e = blockIdx.x * blockDim.x + threadIdx.x;
    if (e < EE) {
        int r = ei[e];
        int c = ei[EE + e];
        float nrm = __ldg(&g_dinv[r]) * ew[e] * __ldg(&g_dinv[c]);
        int pos = atomicAdd(&g_cursor[c], 1);
        g_edge[pos] = make_int2(r, __float_as_int(nrm));
    }
}

// ---------------- mma.sync fp16 GEMM (single pass): outh = fp16(A @ W^T) ----
#define PADB 136
#define TILE_B (128 * PADB * 2)
#define SMEM_MMA_TOTAL (2 * TILE_B)

__device__ __forceinline__ void ldsm_x4(uint32_t* r, uint32_t addr) {
    asm volatile("ldmatrix.sync.aligned.m8n8.x4.shared.b16 {%0,%1,%2,%3}, [%4];"
                 : "=r"(r[0]), "=r"(r[1]), "=r"(r[2]), "=r"(r[3]) : "r"(addr));
}
__device__ __forceinline__ void mma_f16(float* c, const uint32_t* a, const uint32_t* b) {
    asm volatile("mma.sync.aligned.m16n8k16.row.col.f32.f16.f16.f32 "
                 "{%0,%1,%2,%3}, {%4,%5,%6,%7}, {%8,%9}, {%0,%1,%2,%3};"
                 : "+f"(c[0]), "+f"(c[1]), "+f"(c[2]), "+f"(c[3])
                 : "r"(a[0]), "r"(a[1]), "r"(a[2]), "r"(a[3]), "r"(b[0]), "r"(b[1]));
}

__global__ __launch_bounds__(256) void k_mma(const __half* __restrict__ Ah,
                                             const __half* __restrict__ Wh,
                                             __half* __restrict__ outh) {
    extern __shared__ char smem[];
    uint32_t sbase = smem_to_u32(smem);
    int tid = threadIdx.x;
    int bm = blockIdx.x * 128;

    #pragma unroll
    for (int it = 0; it < 16; it++) {
        int idx = tid + it * 256;            // 0..4095
        int tile = idx >> 11;
        int g = idx & 2047;
        int r = g >> 4, c8 = g & 15;
        uint32_t dst = (uint32_t)tile * TILE_B + ((uint32_t)r * PADB + (uint32_t)c8 * 8) * 2;
        uint4 v = make_uint4(0, 0, 0, 0);
        if (tile == 0) {
            int gr = bm + r;
            if (gr < NN) v = *(const uint4*)(Ah + (size_t)gr * 128 + c8 * 8);
        } else {
            v = *(const uint4*)(Wh + r * 128 + c8 * 8);
        }
        *(uint4*)(smem + dst) = v;
    }
    __syncthreads();

    int lane = tid & 31, warp = tid >> 5;
    int wm = warp >> 1, wn = warp & 1;

    uint32_t aoff[2];
    #pragma unroll
    for (int mi = 0; mi < 2; mi++) {
        int row = wm * 32 + mi * 16 + (lane & 15);
        aoff[mi] = ((uint32_t)row * PADB + (uint32_t)(lane >> 4) * 8) * 2;
    }
    uint32_t boff[4];
    #pragma unroll
    for (int pi = 0; pi < 4; pi++) {
        int row = wn * 64 + pi * 16 + (lane & 7) + 8 * ((lane >> 4) & 1);
        boff[pi] = ((uint32_t)row * PADB + (uint32_t)((lane >> 3) & 1) * 8) * 2;
    }

    uint32_t sA = sbase, sW = sbase + TILE_B;

    float C[2][8][4];
    #pragma unroll
    for (int mi = 0; mi < 2; mi++)
        #pragma unroll
        for (int ni = 0; ni < 8; ni++)
            #pragma unroll
            for (int q = 0; q < 4; q++) C[mi][ni][q] = 0.0f;

    #pragma unroll
    for (int ks = 0; ks < 8; ks++) {
        uint32_t kadv = (uint32_t)ks * 32;
        uint32_t a[2][4], bw[4][4];
        #pragma unroll
        for (int mi = 0; mi < 2; mi++) ldsm_x4(a[mi], sA + aoff[mi] + kadv);
        #pragma unroll
        for (int pi = 0; pi < 4; pi++) ldsm_x4(bw[pi], sW + boff[pi] + kadv);
        #pragma unroll
        for (int mi = 0; mi < 2; mi++) {
            #pragma unroll
            for (int ni = 0; ni < 8; ni++) {
                mma_f16(C[mi][ni], a[mi], &bw[ni >> 1][(ni & 1) * 2]);
            }
        }
    }

    int g = lane >> 2, ctg = lane & 3;
    #pragma unroll
    for (int mi = 0; mi < 2; mi++) {
        int r0 = bm + wm * 32 + mi * 16 + g;
        #pragma unroll
        for (int ni = 0; ni < 8; ni++) {
            int col = wn * 64 + ni * 8 + ctg * 2;
            if (r0 < NN)
                *(__half2*)&outh[(size_t)r0 * 128 + col] =
                    __floats2half2_rn(C[mi][ni][0], C[mi][ni][1]);
            if (r0 + 8 < NN)
                *(__half2*)&outh[(size_t)(r0 + 8) * 128 + col] =
                    __floats2half2_rn(C[mi][ni][2], C[mi][ni][3]);
        }
    }
}

// ---------------- warp-per-node aggregate + LN + ReLU + residual ------------
// flags: bit0 relu, bit1 residual from fp32 hinf, bit2 write fp32 hout,
//        bit3 write fp16 xh (next-layer input)
__global__ __launch_bounds__(256) void k_agg(const __half* __restrict__ xwh,
                                             const float* __restrict__ hinf,
                                             __half* __restrict__ xh_io,
                                             const float* __restrict__ bias,
                                             const float* __restrict__ gamma,
                                             const float* __restrict__ beta,
                                             float* __restrict__ hout,
                                             int flags) {
    int warp = threadIdx.x >> 5, lane = threadIdx.x & 31;
    int n = blockIdx.x * 8 + warp;     // grid 6250 * 8 = 50000 exact
    int d0 = lane * 4;

    float dinv_c = __ldg(&g_dinv[n]);
    float invdeg = dinv_c * dinv_c;
    uint2 sv = __ldg((const uint2*)(xwh + (size_t)n * DD + d0));
    float2 s01 = __half22float2(*(const __half2*)&sv.x);
    float2 s23 = __half22float2(*(const __half2*)&sv.y);
    float4 bv = __ldg((const float4*)&bias[d0]);
    float a0 = invdeg * s01.x + bv.x;
    float a1 = invdeg * s01.y + bv.y;
    float a2 = invdeg * s23.x + bv.z;
    float a3 = invdeg * s23.y + bv.w;

    int beg = __ldg(&g_rowptr[n]), end = __ldg(&g_rowptr[n + 1]);
    int j = beg;
    for (; j + 7 < end; j += 8) {
        int2 e0 = __ldg(&g_edge[j]);
        int2 e1 = __ldg(&g_edge[j + 1]);
        int2 e2 = __ldg(&g_edge[j + 2]);
        int2 e3 = __ldg(&g_edge[j + 3]);
        int2 e4 = __ldg(&g_edge[j + 4]);
        int2 e5 = __ldg(&g_edge[j + 5]);
        int2 e6 = __ldg(&g_edge[j + 6]);
        int2 e7 = __ldg(&g_edge[j + 7]);
        uint2 v0 = __ldg((const uint2*)(xwh + (size_t)e0.x * DD + d0));
        uint2 v1 = __ldg((const uint2*)(xwh + (size_t)e1.x * DD + d0));
        uint2 v2 = __ldg((const uint2*)(xwh + (size_t)e2.x * DD + d0));
        uint2 v3 = __ldg((const uint2*)(xwh + (size_t)e3.x * DD + d0));
        uint2 v4 = __ldg((const uint2*)(xwh + (size_t)e4.x * DD + d0));
        uint2 v5 = __ldg((const uint2*)(xwh + (size_t)e5.x * DD + d0));
        uint2 v6 = __ldg((const uint2*)(xwh + (size_t)e6.x * DD + d0));
        uint2 v7 = __ldg((const uint2*)(xwh + (size_t)e7.x * DD + d0));
        float w0 = __int_as_float(e0.y), w1 = __int_as_float(e1.y);
        float w2 = __int_as_float(e2.y), w3 = __int_as_float(e3.y);
        float w4 = __int_as_float(e4.y), w5 = __int_as_float(e5.y);
        float w6 = __int_as_float(e6.y), w7 = __int_as_float(e7.y);
        float2 p, q;
        p = __half22float2(*(const __half2*)&v0.x); q = __half22float2(*(const __half2*)&v0.y);
        a0 += w0 * p.x; a1 += w0 * p.y; a2 += w0 * q.x; a3 += w0 * q.y;
        p = __half22float2(*(const __half2*)&v1.x); q = __half22float2(*(const __half2*)&v1.y);
        a0 += w1 * p.x; a1 += w1 * p.y; a2 += w1 * q.x; a3 += w1 * q.y;
        p = __half22float2(*(const __half2*)&v2.x); q = __half22float2(*(const __half2*)&v2.y);
        a0 += w2 * p.x; a1 += w2 * p.y; a2 += w2 * q.x; a3 += w2 * q.y;
        p = __half22float2(*(const __half2*)&v3.x); q = __half22float2(*(const __half2*)&v3.y);
        a0 += w3 * p.x; a1 += w3 * p.y; a2 += w3 * q.x; a3 += w3 * q.y;
        p = __half22float2(*(const __half2*)&v4.x); q = __half22float2(*(const __half2*)&v4.y);
        a0 += w4 * p.x; a1 += w4 * p.y; a2 += w4 * q.x; a3 += w4 * q.y;
        p = __half22float2(*(const __half2*)&v5.x); q = __half22float2(*(const __half2*)&v5.y);
        a0 += w5 * p.x; a1 += w5 * p.y; a2 += w5 * q.x; a3 += w5 * q.y;
        p = __half22float2(*(const __half2*)&v6.x); q = __half22float2(*(const __half2*)&v6.y);
        a0 += w6 * p.x; a1 += w6 * p.y; a2 += w6 * q.x; a3 += w6 * q.y;
        p = __half22float2(*(const __half2*)&v7.x); q = __half22float2(*(const __half2*)&v7.y);
        a0 += w7 * p.x; a1 += w7 * p.y; a2 += w7 * q.x; a3 += w7 * q.y;
    }
    for (; j < end; j++) {
        int2 e = __ldg(&g_edge[j]);
        float w = __int_as_float(e.y);
        uint2 v = __ldg((const uint2*)(xwh + (size_t)e.x * DD + d0));
        float2 p = __half22float2(*(const __half2*)&v.x);
        float2 q = __half22float2(*(const __half2*)&v.y);
        a0 += w * p.x; a1 += w * p.y; a2 += w * q.x; a3 += w * q.y;
    }

    // warp-level LayerNorm over 128 features (4 per lane)
    float s = a0 + a1 + a2 + a3;
    #pragma unroll
    for (int off = 16; off >= 1; off >>= 1) s += __shfl_xor_sync(0xffffffffu, s, off);
    float mu = s * (1.0f / 128.0f);

    float d0f = a0 - mu, d1f = a1 - mu, d2f = a2 - mu, d3f = a3 - mu;
    float q = d0f * d0f + d1f * d1f + d2f * d2f + d3f * d3f;
    #pragma unroll
    for (int off = 16; off >= 1; off >>= 1) q += __shfl_xor_sync(0xffffffffu, q, off);
    float rstd = rsqrtf(q * (1.0f / 128.0f) + LN_EPS);

    float4 gv = __ldg((const float4*)&gamma[d0]);
    float4 bt = __ldg((const float4*)&beta[d0]);
    float y0 = d0f * rstd * gv.x + bt.x;
    float y1 = d1f * rstd * gv.y + bt.y;
    float y2 = d2f * rstd * gv.z + bt.z;
    float y3 = d3f * rstd * gv.w + bt.w;
    if (flags & 1) {
        y0 = fmaxf(y0, 0.0f); y1 = fmaxf(y1, 0.0f);
        y2 = fmaxf(y2, 0.0f); y3 = fmaxf(y3, 0.0f);
    }

    if (flags & 2) {
        float4 hv = __ldg((const float4*)&hinf[(size_t)n * DD + d0]);
        y0 += hv.x; y1 += hv.y; y2 += hv.z; y3 += hv.w;
    } else {
        uint2 hv = __ldg((const uint2*)(xh_io + (size_t)n * DD + d0));
        float2 h01 = __half22float2(*(const __half2*)&hv.x);
        float2 h23 = __half22float2(*(const __half2*)&hv.y);
        y0 += h01.x; y1 += h01.y; y2 += h23.x; y3 += h23.y;
    }

    if (flags & 4)
        *(float4*)&hout[(size_t)n * DD + d0] = make_float4(y0, y1, y2, y3);
    if (flags & 8) {
        size_t i = (size_t)n * DD + d0;
        __half2 h01 = __floats2half2_rn(y0, y1);
        __half2 h23 = __floats2half2_rn(y2, y3);
        *(uint2*)&xh_io[i] = make_uint2(*(uint32_t*)&h01, *(uint32_t*)&h23);
    }
}

// ---------------- launch ----------------------------------------------------
extern "C" void kernel_launch(void* const* d_in, const int* in_sizes, int n_in,
                              void* d_out, int out_size) {
    const float* x      = (const float*)d_in[0];
    const int*   ei     = (const int*)  d_in[1];
    const float* ew     = (const float*)d_in[2];
    const float* Ws     = (const float*)d_in[3];
    const float* bs     = (const float*)d_in[4];
    const float* gammas = (const float*)d_in[5];
    const float* betas  = (const float*)d_in[6];
    float* out = (float*)d_out;

    __half* xwh = nullptr; cudaGetSymbolAddress((void**)&xwh, g_xwh);
    __half* xh  = nullptr; cudaGetSymbolAddress((void**)&xh, g_xh);
    __half* Wh  = nullptr; cudaGetSymbolAddress((void**)&Wh, g_Wh);
    float* degp = nullptr; cudaGetSymbolAddress((void**)&degp, g_deg);
    int*   cntp = nullptr; cudaGetSymbolAddress((void**)&cntp, g_cnt);
    void*  sstp = nullptr; cudaGetSymbolAddress(&sstp, g_sstate);

    cudaFuncSetAttribute(k_mma, cudaFuncAttributeMaxDynamicSharedMemorySize, SMEM_MMA_TOTAL);

    static cudaStream_t s2 = nullptr;
    static cudaEvent_t evFork = nullptr, evJoin = nullptr;
    if (!s2) {
        cudaStreamCreateWithFlags(&s2, cudaStreamNonBlocking);
        cudaEventCreateWithFlags(&evFork, cudaEventDisableTiming);
        cudaEventCreateWithFlags(&evJoin, cudaEventDisableTiming);
    }

    int gE = (EE + 255) / 256;                 // 6250
    int gConv = 25192;
    int gMma = (NN + 127) / 128;
    int gAgg = NN / 8;

    // fork at the very start: conversion + layer-0 GEMM on stream 2
    cudaEventRecord(evFork, 0);
    cudaStreamWaitEvent(s2, evFork, 0);
    k_conv<<<gConv, 256, 0, s2>>>(x, Ws);
    k_mma<<<gMma, 256, SMEM_MMA_TOTAL, s2>>>(xh, Wh + 0 * DD * DD, xwh);
    cudaEventRecord(evJoin, s2);

    // graph build on the main stream
    cudaMemsetAsync(degp, 0, NN * sizeof(float));
    cudaMemsetAsync(cntp, 0, NN * sizeof(int));
    cudaMemsetAsync(sstp, 0, SCAN_B * sizeof(unsigned long long));
    k_degcnt<<<gE, 256>>>(ei, ew);
    k_scan<<<SCAN_B, 1024>>>();
    k_fill<<<gE, 256>>>(ei, ew);
    cudaStreamWaitEvent(0, evJoin, 0);

    // layer 0: residual from fp32 x; write fp16 xh only
    k_agg<<<gAgg, 256>>>(xwh, x, xh, bs + 0 * DD, gammas + 0 * DD, betas + 0 * DD, out, 1 | 2 | 8);
    // layer 1: residual fp16 xh; write fp16 xh
    k_mma<<<gMma, 256, SMEM_MMA_TOTAL>>>(xh, Wh + 1 * DD * DD, xwh);
    k_agg<<<gAgg, 256>>>(xwh, x, xh, bs + 1 * DD, gammas + 1 * DD, betas + 1 * DD, out, 1 | 8);
    // layer 2: residual fp16 xh; write fp32 out
    k_mma<<<gMma, 256, SMEM_MMA_TOTAL>>>(xh, Wh + 2 * DD * DD, xwh);
    k_agg<<<gAgg, 256>>>(xwh, x, xh, bs + 2 * DD, gammas + 2 * DD, betas + 2 * DD, out, 4);
}

// round 16
// speedup vs baseline: 1.2648x; 1.0112x over previous
#include <cuda_runtime.h>
#include <cuda_bf16.h>
#include <cuda_fp16.h>
#include <cstdint>

#define NN 50000
#define EE 1600000
#define DD 128
#define LN_EPS 1e-5f
#define SCAN_B 49   // ceil(NN / 1024)

// ---------------- scratch (static device globals) ---------------------------
__device__ unsigned long long g_pk[NN];           // (cnt<<32) | deg_fixed(2^20)
__device__ float g_dinv[NN];
__device__ int   g_rowptr[NN + 1];
__device__ int   g_cursor[NN];
__device__ unsigned long long g_sstate[SCAN_B];   // lookback state (flag<<32 | value)
__device__ int2  g_edge[EE];                      // (src, norm bits)
__device__ __half g_xwh[(size_t)NN * DD];         // fp16 GEMM output (gather source)
__device__ __half g_xh[(size_t)NN * DD];          // fp16 current h (GEMM input + residual)
__device__ __half g_Wh[3 * DD * DD];              // fp16 weights

__device__ __forceinline__ uint32_t smem_to_u32(const void* p) {
    uint32_t a;
    asm("{ .reg .u64 t; cvta.to.shared.u64 t, %1; cvt.u32.u64 %0, t; }" : "=r"(a) : "l"(p));
    return a;
}

// ---------------- fp16 conversion (stream 2, overlaps graph build) -----------
__global__ __launch_bounds__(256) void k_conv(const float* __restrict__ x,
                                              const float* __restrict__ Ws) {
    int b = blockIdx.x, t = threadIdx.x;
    if (b < 25000) {
        int i = b * 256 + t;
        g_xh[i] = __float2half_rn(x[i]);
    } else {
        int j = (b - 25000) * 256 + t;     // < 49152
        g_Wh[j] = __float2half_rn(Ws[j]);
    }
}

// ---------------- packed degree+count histogram (1 atomic/edge) --------------
__global__ void k_degcnt(const int* __restrict__ ei, const float* __restrict__ ew) {
    int e = blockIdx.x * blockDim.x + threadIdx.x;
    if (e < EE) {
        int c = ei[EE + e];
        unsigned int fx = __float2uint_rn(ew[e] * 1048576.0f);   // 2^20 fixed point
        atomicAdd(&g_pk[c], (1ULL << 32) | (unsigned long long)fx);
    }
}

// ---------------- single-pass lookback scan + cursor + dinv ------------------
__global__ __launch_bounds__(1024) void k_scan() {
    __shared__ int s_w[32];
    __shared__ int s_exc;
    int b = blockIdx.x, t = threadIdx.x, lane = t & 31, wid = t >> 5;
    int i = b * 1024 + t;
    unsigned long long pk = (i < NN) ? g_pk[i] : 0ULL;
    int v = (int)(pk >> 32);
    int incl = v;
    #pragma unroll
    for (int off = 1; off < 32; off <<= 1) {
        int u = __shfl_up_sync(0xffffffffu, incl, off);
        if (lane >= off) incl += u;
    }
    if (lane == 31) s_w[wid] = incl;
    __syncthreads();
    if (wid == 0) {
        int w = s_w[lane];
        #pragma unroll
        for (int off = 1; off < 32; off <<= 1) {
            int u = __shfl_up_sync(0xffffffffu, w, off);
            if (lane >= off) w += u;
        }
        s_w[lane] = w;
    }
    __syncthreads();
    int base = (wid == 0) ? 0 : s_w[wid - 1];
    unsigned int A = (unsigned int)s_w[31];

    if (t == 0) {
        if (b == 0) {
            atomicExch(&g_sstate[0], (2ULL << 32) | A);
            s_exc = 0;
        } else {
            atomicExch(&g_sstate[b], (1ULL << 32) | A);
            unsigned int exc = 0;
            int idx = b - 1;
            while (true) {
                unsigned long long s = *((volatile unsigned long long*)&g_sstate[idx]);
                unsigned int f = (unsigned int)(s >> 32);
                if (f == 2u) { exc += (unsigned int)s; break; }
                if (f == 1u) { exc += (unsigned int)s; idx--; }
            }
            atomicExch(&g_sstate[b], (2ULL << 32) | (exc + A));
            s_exc = (int)exc;
        }
    }
    __syncthreads();
    if (i < NN) {
        int rp = s_exc + base + incl - v;
        g_rowptr[i] = rp;
        g_cursor[i] = rp;
        float dg = (float)(unsigned int)pk * (1.0f / 1048576.0f) + 1.0f;  // + self loop
        g_dinv[i] = rsqrtf(dg);
        if (i == 0) g_rowptr[NN] = EE;
    }
}

// ---------------- CSR fill with precomputed norm -----------------------------
__global__ void k_fill(const int* __restrict__ ei, const float* __restrict__ ew) {
    int e = blockIdx.x * blockDim.x + threadIdx.x;
    if (e < EE) {
        int r = ei[e];
        int c = ei[EE + e];
        float nrm = __ldg(&g_dinv[r]) * ew[e] * __ldg(&g_dinv[c]);
        int pos = atomicAdd(&g_cursor[c], 1);
        g_edge[pos] = make_int2(r, __float_as_int(nrm));
    }
}

// ---------------- mma.sync fp16 GEMM (single pass): outh = fp16(A @ W^T) ----
#define PADB 136
#define TILE_B (128 * PADB * 2)
#define SMEM_MMA_TOTAL (2 * TILE_B)

__device__ __forceinline__ void ldsm_x4(uint32_t* r, uint32_t addr) {
    asm volatile("ldmatrix.sync.aligned.m8n8.x4.shared.b16 {%0,%1,%2,%3}, [%4];"
                 : "=r"(r[0]), "=r"(r[1]), "=r"(r[2]), "=r"(r[3]) : "r"(addr));
}
__device__ __forceinline__ void mma_f16(float* c, const uint32_t* a, const uint32_t* b) {
    asm volatile("mma.sync.aligned.m16n8k16.row.col.f32.f16.f16.f32 "
                 "{%0,%1,%2,%3}, {%4,%5,%6,%7}, {%8,%9}, {%0,%1,%2,%3};"
                 : "+f"(c[0]), "+f"(c[1]), "+f"(c[2]), "+f"(c[3])
                 : "r"(a[0]), "r"(a[1]), "r"(a[2]), "r"(a[3]), "r"(b[0]), "r"(b[1]));
}

__global__ __launch_bounds__(256) void k_mma(const __half* __restrict__ Ah,
                                             const __half* __restrict__ Wh,
                                             __half* __restrict__ outh,
                                             int bm0) {
    extern __shared__ char smem[];
    uint32_t sbase = smem_to_u32(smem);
    int tid = threadIdx.x;
    int bm = (blockIdx.x + bm0) * 128;

    #pragma unroll
    for (int it = 0; it < 16; it++) {
        int idx = tid + it * 256;            // 0..4095
        int tile = idx >> 11;
        int g = idx & 2047;
        int r = g >> 4, c8 = g & 15;
        uint32_t dst = (uint32_t)tile * TILE_B + ((uint32_t)r * PADB + (uint32_t)c8 * 8) * 2;
        uint4 v = make_uint4(0, 0, 0, 0);
        if (tile == 0) {
            int gr = bm + r;
            if (gr < NN) v = *(const uint4*)(Ah + (size_t)gr * 128 + c8 * 8);
        } else {
            v = *(const uint4*)(Wh + r * 128 + c8 * 8);
        }
        *(uint4*)(smem + dst) = v;
    }
    __syncthreads();

    int lane = tid & 31, warp = tid >> 5;
    int wm = warp >> 1, wn = warp & 1;

    uint32_t aoff[2];
    #pragma unroll
    for (int mi = 0; mi < 2; mi++) {
        int row = wm * 32 + mi * 16 + (lane & 15);
        aoff[mi] = ((uint32_t)row * PADB + (uint32_t)(lane >> 4) * 8) * 2;
    }
    uint32_t boff[4];
    #pragma unroll
    for (int pi = 0; pi < 4; pi++) {
        int row = wn * 64 + pi * 16 + (lane & 7) + 8 * ((lane >> 4) & 1);
        boff[pi] = ((uint32_t)row * PADB + (uint32_t)((lane >> 3) & 1) * 8) * 2;
    }

    uint32_t sA = sbase, sW = sbase + TILE_B;

    float C[2][8][4];
    #pragma unroll
    for (int mi = 0; mi < 2; mi++)
        #pragma unroll
        for (int ni = 0; ni < 8; ni++)
            #pragma unroll
            for (int q = 0; q < 4; q++) C[mi][ni][q] = 0.0f;

    #pragma unroll
    for (int ks = 0; ks < 8; ks++) {
        uint32_t kadv = (uint32_t)ks * 32;
        uint32_t a[2][4], bw[4][4];
        #pragma unroll
        for (int mi = 0; mi < 2; mi++) ldsm_x4(a[mi], sA + aoff[mi] + kadv);
        #pragma unroll
        for (int pi = 0; pi < 4; pi++) ldsm_x4(bw[pi], sW + boff[pi] + kadv);
        #pragma unroll
        for (int mi = 0; mi < 2; mi++) {
            #pragma unroll
            for (int ni = 0; ni < 8; ni++) {
                mma_f16(C[mi][ni], a[mi], &bw[ni >> 1][(ni & 1) * 2]);
            }
        }
    }

    int g = lane >> 2, ctg = lane & 3;
    #pragma unroll
    for (int mi = 0; mi < 2; mi++) {
        int r0 = bm + wm * 32 + mi * 16 + g;
        #pragma unroll
        for (int ni = 0; ni < 8; ni++) {
            int col = wn * 64 + ni * 8 + ctg * 2;
            if (r0 < NN)
                *(__half2*)&outh[(size_t)r0 * 128 + col] =
                    __floats2half2_rn(C[mi][ni][0], C[mi][ni][1]);
            if (r0 + 8 < NN)
                *(__half2*)&outh[(size_t)(r0 + 8) * 128 + col] =
                    __floats2half2_rn(C[mi][ni][2], C[mi][ni][3]);
        }
    }
}

// ---------------- warp-per-node aggregate + LN + ReLU + residual ------------
// flags: bit0 relu, bit1 residual from fp32 hinf, bit2 write fp32 hout,
//        bit3 write fp16 xh (next-layer input)
__global__ __launch_bounds__(256) void k_agg(const __half* __restrict__ xwh,
                                             const float* __restrict__ hinf,
                                             __half* __restrict__ xh_io,
                                             const float* __restrict__ bias,
                                             const float* __restrict__ gamma,
                                             const float* __restrict__ beta,
                                             float* __restrict__ hout,
                                             int flags, int boff) {
    int warp = threadIdx.x >> 5, lane = threadIdx.x & 31;
    int n = (blockIdx.x + boff) * 8 + warp;
    int d0 = lane * 4;

    float dinv_c = __ldg(&g_dinv[n]);
    float invdeg = dinv_c * dinv_c;
    uint2 sv = __ldg((const uint2*)(xwh + (size_t)n * DD + d0));
    float2 s01 = __half22float2(*(const __half2*)&sv.x);
    float2 s23 = __half22float2(*(const __half2*)&sv.y);
    float4 bv = __ldg((const float4*)&bias[d0]);
    float a0 = invdeg * s01.x + bv.x;
    float a1 = invdeg * s01.y + bv.y;
    float a2 = invdeg * s23.x + bv.z;
    float a3 = invdeg * s23.y + bv.w;

    int beg = __ldg(&g_rowptr[n]), end = __ldg(&g_rowptr[n + 1]);
    int j = beg;
    for (; j + 7 < end; j += 8) {
        int2 e0 = __ldg(&g_edge[j]);
        int2 e1 = __ldg(&g_edge[j + 1]);
        int2 e2 = __ldg(&g_edge[j + 2]);
        int2 e3 = __ldg(&g_edge[j + 3]);
        int2 e4 = __ldg(&g_edge[j + 4]);
        int2 e5 = __ldg(&g_edge[j + 5]);
        int2 e6 = __ldg(&g_edge[j + 6]);
        int2 e7 = __ldg(&g_edge[j + 7]);
        uint2 v0 = __ldg((const uint2*)(xwh + (size_t)e0.x * DD + d0));
        uint2 v1 = __ldg((const uint2*)(xwh + (size_t)e1.x * DD + d0));
        uint2 v2 = __ldg((const uint2*)(xwh + (size_t)e2.x * DD + d0));
        uint2 v3 = __ldg((const uint2*)(xwh + (size_t)e3.x * DD + d0));
        uint2 v4 = __ldg((const uint2*)(xwh + (size_t)e4.x * DD + d0));
        uint2 v5 = __ldg((const uint2*)(xwh + (size_t)e5.x * DD + d0));
        uint2 v6 = __ldg((const uint2*)(xwh + (size_t)e6.x * DD + d0));
        uint2 v7 = __ldg((const uint2*)(xwh + (size_t)e7.x * DD + d0));
        float w0 = __int_as_float(e0.y), w1 = __int_as_float(e1.y);
        float w2 = __int_as_float(e2.y), w3 = __int_as_float(e3.y);
        float w4 = __int_as_float(e4.y), w5 = __int_as_float(e5.y);
        float w6 = __int_as_float(e6.y), w7 = __int_as_float(e7.y);
        float2 p, q;
        p = __half22float2(*(const __half2*)&v0.x); q = __half22float2(*(const __half2*)&v0.y);
        a0 += w0 * p.x; a1 += w0 * p.y; a2 += w0 * q.x; a3 += w0 * q.y;
        p = __half22float2(*(const __half2*)&v1.x); q = __half22float2(*(const __half2*)&v1.y);
        a0 += w1 * p.x; a1 += w1 * p.y; a2 += w1 * q.x; a3 += w1 * q.y;
        p = __half22float2(*(const __half2*)&v2.x); q = __half22float2(*(const __half2*)&v2.y);
        a0 += w2 * p.x; a1 += w2 * p.y; a2 += w2 * q.x; a3 += w2 * q.y;
        p = __half22float2(*(const __half2*)&v3.x); q = __half22float2(*(const __half2*)&v3.y);
        a0 += w3 * p.x; a1 += w3 * p.y; a2 += w3 * q.x; a3 += w3 * q.y;
        p = __half22float2(*(const __half2*)&v4.x); q = __half22float2(*(const __half2*)&v4.y);
        a0 += w4 * p.x; a1 += w4 * p.y; a2 += w4 * q.x; a3 += w4 * q.y;
        p = __half22float2(*(const __half2*)&v5.x); q = __half22float2(*(const __half2*)&v5.y);
        a0 += w5 * p.x; a1 += w5 * p.y; a2 += w5 * q.x; a3 += w5 * q.y;
        p = __half22float2(*(const __half2*)&v6.x); q = __half22float2(*(const __half2*)&v6.y);
        a0 += w6 * p.x; a1 += w6 * p.y; a2 += w6 * q.x; a3 += w6 * q.y;
        p = __half22float2(*(const __half2*)&v7.x); q = __half22float2(*(const __half2*)&v7.y);
        a0 += w7 * p.x; a1 += w7 * p.y; a2 += w7 * q.x; a3 += w7 * q.y;
    }
    for (; j < end; j++) {
        int2 e = __ldg(&g_edge[j]);
        float w = __int_as_float(e.y);
        uint2 v = __ldg((const uint2*)(xwh + (size_t)e.x * DD + d0));
        float2 p = __half22float2(*(const __half2*)&v.x);
        float2 q = __half22float2(*(const __half2*)&v.y);
        a0 += w * p.x; a1 += w * p.y; a2 += w * q.x; a3 += w * q.y;
    }

    // warp-level LayerNorm over 128 features (4 per lane)
    float s = a0 + a1 + a2 + a3;
    #pragma unroll
    for (int off = 16; off >= 1; off >>= 1) s += __shfl_xor_sync(0xffffffffu, s, off);
    float mu = s * (1.0f / 128.0f);

    float d0f = a0 - mu, d1f = a1 - mu, d2f = a2 - mu, d3f = a3 - mu;
    float q = d0f * d0f + d1f * d1f + d2f * d2f + d3f * d3f;
    #pragma unroll
    for (int off = 16; off >= 1; off >>= 1) q += __shfl_xor_sync(0xffffffffu, q, off);
    float rstd = rsqrtf(q * (1.0f / 128.0f) + LN_EPS);

    float4 gv = __ldg((const float4*)&gamma[d0]);
    float4 bt = __ldg((const float4*)&beta[d0]);
    float y0 = d0f * rstd * gv.x + bt.x;
    float y1 = d1f * rstd * gv.y + bt.y;
    float y2 = d2f * rstd * gv.z + bt.z;
    float y3 = d3f * rstd * gv.w + bt.w;
    if (flags & 1) {
        y0 = fmaxf(y0, 0.0f); y1 = fmaxf(y1, 0.0f);
        y2 = fmaxf(y2, 0.0f); y3 = fmaxf(y3, 0.0f);
    }

    if (flags & 2) {
        float4 hv = __ldg((const float4*)&hinf[(size_t)n * DD + d0]);
        y0 += hv.x; y1 += hv.y; y2 += hv.z; y3 += hv.w;
    } else {
        uint2 hv = __ldg((const uint2*)(xh_io + (size_t)n * DD + d0));
        float2 h01 = __half22float2(*(const __half2*)&hv.x);
        float2 h23 = __half22float2(*(const __half2*)&hv.y);
        y0 += h01.x; y1 += h01.y; y2 += h23.x; y3 += h23.y;
    }

    if (flags & 4)
        *(float4*)&hout[(size_t)n * DD + d0] = make_float4(y0, y1, y2, y3);
    if (flags & 8) {
        size_t i = (size_t)n * DD + d0;
        __half2 h01 = __floats2half2_rn(y0, y1);
        __half2 h23 = __floats2half2_rn(y2, y3);
        *(uint2*)&xh_io[i] = make_uint2(*(uint32_t*)&h01, *(uint32_t*)&h23);
    }
}

// ---------------- launch ----------------------------------------------------
extern "C" void kernel_launch(void* const* d_in, const int* in_sizes, int n_in,
                              void* d_out, int out_size) {
    const float* x      = (const float*)d_in[0];
    const int*   ei     = (const int*)  d_in[1];
    const float* ew     = (const float*)d_in[2];
    const float* Ws     = (const float*)d_in[3];
    const float* bs     = (const float*)d_in[4];
    const float* gammas = (const float*)d_in[5];
    const float* betas  = (const float*)d_in[6];
    float* out = (float*)d_out;

    __half* xwh = nullptr; cudaGetSymbolAddress((void**)&xwh, g_xwh);
    __half* xh  = nullptr; cudaGetSymbolAddress((void**)&xh, g_xh);
    __half* Wh  = nullptr; cudaGetSymbolAddress((void**)&Wh, g_Wh);
    void*  pkp  = nullptr; cudaGetSymbolAddress(&pkp, g_pk);
    void*  sstp = nullptr; cudaGetSymbolAddress(&sstp, g_sstate);

    cudaFuncSetAttribute(k_mma, cudaFuncAttributeMaxDynamicSharedMemorySize, SMEM_MMA_TOTAL);

    static cudaStream_t s2 = nullptr;
    static cudaEvent_t evFork = nullptr, evJoin = nullptr;
    static cudaEvent_t e0A = nullptr, eM1A = nullptr, e1A = nullptr, eM2A = nullptr;
    if (!s2) {
        cudaStreamCreateWithFlags(&s2, cudaStreamNonBlocking);
        cudaEventCreateWithFlags(&evFork, cudaEventDisableTiming);
        cudaEventCreateWithFlags(&evJoin, cudaEventDisableTiming);
        cudaEventCreateWithFlags(&e0A, cudaEventDisableTiming);
        cudaEventCreateWithFlags(&eM1A, cudaEventDisableTiming);
        cudaEventCreateWithFlags(&e1A, cudaEventDisableTiming);
        cudaEventCreateWithFlags(&eM2A, cudaEventDisableTiming);
    }

    int gE = (EE + 255) / 256;                 // 6250
    int gConv = 25192;
    int gMma = (NN + 127) / 128;               // 391
    const int MMA_A = 196, MMA_B = 195;        // rows [0,25088) / [25088,50000)
    const int AGG_A = 3136, AGG_B = 3114;      // nodes [0,25088) / [25088,50000)

    // fork at the very start: conversion + full layer-0 GEMM on stream 2
    cudaEventRecord(evFork, 0);
    cudaStreamWaitEvent(s2, evFork, 0);
    k_conv<<<gConv, 256, 0, s2>>>(x, Ws);
    k_mma<<<gMma, 256, SMEM_MMA_TOTAL, s2>>>(xh, Wh + 0 * DD * DD, xwh, 0);
    cudaEventRecord(evJoin, s2);

    // graph build on the main stream
    cudaMemsetAsync(pkp, 0, NN * sizeof(unsigned long long));
    cudaMemsetAsync(sstp, 0, SCAN_B * sizeof(unsigned long long));
    k_degcnt<<<gE, 256>>>(ei, ew);
    k_scan<<<SCAN_B, 1024>>>();
    k_fill<<<gE, 256>>>(ei, ew);
    cudaStreamWaitEvent(0, evJoin, 0);

    // ---- layer 0: agg split into halves; mma1A overlaps agg0B ----
    k_agg<<<AGG_A, 256>>>(xwh, x, xh, bs + 0 * DD, gammas + 0 * DD, betas + 0 * DD, out, 1 | 2 | 8, 0);
    cudaEventRecord(e0A, 0);
    k_agg<<<AGG_B, 256>>>(xwh, x, xh, bs + 0 * DD, gammas + 0 * DD, betas + 0 * DD, out, 1 | 2 | 8, AGG_A);
    cudaStreamWaitEvent(s2, e0A, 0);
    k_mma<<<MMA_A, 256, SMEM_MMA_TOTAL, s2>>>(xh, Wh + 1 * DD * DD, xwh, 0);
    cudaEventRecord(eM1A, s2);
    k_mma<<<MMA_B, 256, SMEM_MMA_TOTAL>>>(xh, Wh + 1 * DD * DD, xwh, MMA_A);
    cudaStreamWaitEvent(0, eM1A, 0);

    // ---- layer 1: same pipelining for mma2 ----
    k_agg<<<AGG_A, 256>>>(xwh, x, xh, bs + 1 * DD, gammas + 1 * DD, betas + 1 * DD, out, 1 | 8, 0);
    cudaEventRecord(e1A, 0);
    k_agg<<<AGG_B, 256>>>(xwh, x, xh, bs + 1 * DD, gammas + 1 * DD, betas + 1 * DD, out, 1 | 8, AGG_A);
    cudaStreamWaitEvent(s2, e1A, 0);
    k_mma<<<MMA_A, 256, SMEM_MMA_TOTAL, s2>>>(xh, Wh + 2 * DD * DD, xwh, 0);
    cudaEventRecord(eM2A, s2);
    k_mma<<<MMA_B, 256, SMEM_MMA_TOTAL>>>(xh, Wh + 2 * DD * DD, xwh, MMA_A);
    cudaStreamWaitEvent(0, eM2A, 0);

    // ---- layer 2 ----
    k_agg<<<NN / 8, 256>>>(xwh, x, xh, bs + 2 * DD, gammas + 2 * DD, betas + 2 * DD, out, 4, 0);
}